// round 1
// baseline (speedup 1.0000x reference)
#include <cuda_runtime.h>
#include <cuda_bf16.h>

// ---------------- dims ----------------
#define BZ   4
#define LSEQ 4096
#define DM   64
#define DI   128
#define DS   16
#define DTR  4
#define NDBL 36      // DTR + 2*DS
#define NCONV 4
#define NIN  57
#define NOUT 6
#define NCH  64      // chunks
#define TC   64      // chunk length (NCH*TC = LSEQ)
#define NTOK (BZ*LSEQ)

// ---------------- scratch (device globals; no runtime alloc) ----------------
__device__ float g_h[NTOK*DM];          //  4.2 MB
__device__ float g_xz[NTOK*2*DI];       // 16.8 MB  (xp | z)
__device__ float g_u[NTOK*DI];          //  8.4 MB
__device__ float g_delta[NTOK*DI];      //  8.4 MB
__device__ float g_Bm[NTOK*DS];         //  1.0 MB
__device__ float g_Cm[NTOK*DS];         //  1.0 MB
__device__ float g_P[BZ*NCH*DI*DS];     //  2.1 MB
__device__ float g_F[BZ*NCH*DI*DS];     //  2.1 MB
__device__ float g_hin[BZ*NCH*DI*DS];   //  2.1 MB
__device__ float g_y[NTOK*DI];          //  8.4 MB

// ---------------- helpers ----------------
__device__ __forceinline__ unsigned long long pack2(float lo, float hi) {
    unsigned long long r;
    asm("mov.b64 %0, {%1, %2};" : "=l"(r) : "f"(lo), "f"(hi));
    return r;
}
__device__ __forceinline__ void unpack2(unsigned long long v, float& lo, float& hi) {
    asm("mov.b64 {%0, %1}, %2;" : "=f"(lo), "=f"(hi) : "l"(v));
}
__device__ __forceinline__ float silu_f(float x) {
    return x / (1.f + __expf(-x));
}
__device__ __forceinline__ float softplus_f(float x) {
    return (x > 20.f) ? x : log1pf(__expf(x));
}

// ---------------- K0: h = x @ w_in.T + b_in ----------------
__global__ void __launch_bounds__(256) k_linear_in(const float* __restrict__ x,
                                                   const float* __restrict__ w,
                                                   const float* __restrict__ bias) {
    __shared__ float sw[DM*NIN];
    __shared__ float sb[DM];
    __shared__ float sx[4*NIN];
    int tid = threadIdx.x;
    for (int i = tid; i < DM*NIN; i += 256) sw[i] = w[i];
    if (tid < DM) sb[tid] = bias[tid];
    int t4 = tid >> 6, j = tid & 63;
    int tok0 = blockIdx.x * 64;
    for (int g = 0; g < 16; ++g) {
        __syncthreads();
        for (int i = tid; i < 4*NIN; i += 256) {
            int tt = i / NIN, k = i % NIN;
            sx[i] = x[(tok0 + g*4 + tt)*NIN + k];
        }
        __syncthreads();
        float acc = sb[j];
        #pragma unroll
        for (int k = 0; k < NIN; k++) acc += sx[t4*NIN + k] * sw[j*NIN + k];
        g_h[(tok0 + g*4 + t4)*DM + j] = acc;
    }
}

// ---------------- K1: xz = h @ in_proj_w.T  (thread = output channel o) ----------------
__global__ void __launch_bounds__(256) k_in_proj(const float* __restrict__ W) {
    __shared__ float sh[32*DM];
    int tid = threadIdx.x;
    unsigned long long w2[DM/2];
    #pragma unroll
    for (int k = 0; k < DM/2; k++)
        w2[k] = pack2(W[tid*DM + 2*k], W[tid*DM + 2*k + 1]);
    int tok0 = blockIdx.x * 32;
    for (int i = tid; i < 32*DM; i += 256) sh[i] = g_h[tok0*DM + i];
    __syncthreads();
    for (int t = 0; t < 32; t++) {
        const unsigned long long* hv = (const unsigned long long*)(sh + t*DM);
        unsigned long long acc2 = 0ull;
        #pragma unroll
        for (int k = 0; k < DM/2; k++)
            asm("fma.rn.f32x2 %0, %1, %2, %0;" : "+l"(acc2) : "l"(hv[k]), "l"(w2[k]));
        float a, b; unpack2(acc2, a, b);
        g_xz[(tok0 + t)*(2*DI) + tid] = a + b;
    }
}

// ---------------- K2: conv+silu -> u; dbl = u@x_proj.T; delta = softplus(dt@dtw.T+b) ----------------
__global__ void __launch_bounds__(256) k_pre(const float* __restrict__ cw,
                                             const float* __restrict__ cb,
                                             const float* __restrict__ xpw,
                                             const float* __restrict__ dpw,
                                             const float* __restrict__ dpb) {
    __shared__ float su[32*DI];        // 16 KB
    __shared__ float swx[DI*NDBL];     // transposed [k][j], 18 KB
    __shared__ float sdt[32*DTR];
    __shared__ float sdw[DI*DTR];
    __shared__ float sdb[DI];
    int tid = threadIdx.x;
    for (int i = tid; i < DI*NDBL; i += 256) {
        int j = i / DI, k = i % DI;
        swx[k*NDBL + j] = xpw[i];
    }
    for (int i = tid; i < DI*DTR; i += 256) sdw[i] = dpw[i];
    if (tid < DI) sdb[tid] = dpb[tid];
    __syncthreads();
    int tok0 = blockIdx.x * 32;
    // step A: depthwise causal conv + silu
    for (int i = tid; i < 32*DI; i += 256) {
        int t = i >> 7, d = i & 127;
        int tok = tok0 + t;
        int b = tok >> 12, l = tok & 4095;
        float acc = cb[d];
        #pragma unroll
        for (int k = 0; k < NCONV; k++) {
            int lp = l - 3 + k;
            float v = (lp >= 0) ? g_xz[((b << 12) + lp)*(2*DI) + d] : 0.f;
            acc += cw[d*NCONV + k] * v;
        }
        float u = silu_f(acc);
        su[i] = u;
        g_u[tok*DI + d] = u;
    }
    __syncthreads();
    // step B: dbl = u @ xpw.T (36 outputs per token)
    for (int idx = tid; idx < 32*NDBL; idx += 256) {
        int t = idx / NDBL, j = idx % NDBL;
        float acc = 0.f;
        const float4* uv = (const float4*)(su + t*DI);
        #pragma unroll
        for (int k4 = 0; k4 < DI/4; k4++) {
            float4 u4 = uv[k4];
            int k = k4 * 4;
            acc += u4.x * swx[(k+0)*NDBL + j] + u4.y * swx[(k+1)*NDBL + j]
                 + u4.z * swx[(k+2)*NDBL + j] + u4.w * swx[(k+3)*NDBL + j];
        }
        int tok = tok0 + t;
        if (j < DTR)            sdt[t*DTR + j] = acc;
        else if (j < DTR + DS)  g_Bm[tok*DS + (j - DTR)] = acc;
        else                    g_Cm[tok*DS + (j - DTR - DS)] = acc;
    }
    __syncthreads();
    // step C: delta
    for (int i = tid; i < 32*DI; i += 256) {
        int t = i >> 7, d = i & 127;
        float s = sdb[d];
        #pragma unroll
        for (int r = 0; r < DTR; r++) s += sdt[t*DTR + r] * sdw[d*DTR + r];
        g_delta[(tok0 + t)*DI + d] = softplus_f(s);
    }
}

// ---------------- K3: scan phase 1 — per chunk (P, F) ----------------
__global__ void __launch_bounds__(512) k_scan1(const float* __restrict__ Alog) {
    int tid = threadIdx.x;
    int d = tid >> 2, ng = tid & 3;
    int b = blockIdx.x / NCH, c = blockIdx.x % NCH;
    const float* al = Alog + d*DS + ng*4;
    float A0 = -__expf(al[0]), A1 = -__expf(al[1]);
    float A2 = -__expf(al[2]), A3 = -__expf(al[3]);
    float F0 = 0.f, F1 = 0.f, F2 = 0.f, F3 = 0.f, S = 0.f;
    int base = b*LSEQ + c*TC;
    float de = g_delta[base*DI + d];
    float uu = g_u[base*DI + d];
    float4 Bv = *(const float4*)(g_Bm + base*DS + ng*4);
    #pragma unroll 2
    for (int i = 0; i < TC; i++) {
        float de_c = de, uu_c = uu; float4 B_c = Bv;
        int ln = base + ((i + 1 < TC) ? (i + 1) : i);
        de = g_delta[ln*DI + d];
        uu = g_u[ln*DI + d];
        Bv = *(const float4*)(g_Bm + ln*DS + ng*4);
        float du = de_c * uu_c;
        S += de_c;
        F0 = __expf(de_c*A0)*F0 + du*B_c.x;
        F1 = __expf(de_c*A1)*F1 + du*B_c.y;
        F2 = __expf(de_c*A2)*F2 + du*B_c.z;
        F3 = __expf(de_c*A3)*F3 + du*B_c.w;
    }
    int o = ((b*NCH + c)*DI + d)*DS + ng*4;
    *(float4*)(g_F + o) = make_float4(F0, F1, F2, F3);
    *(float4*)(g_P + o) = make_float4(__expf(A0*S), __expf(A1*S), __expf(A2*S), __expf(A3*S));
}

// ---------------- K4: inter-chunk carry ----------------
__global__ void __launch_bounds__(512) k_carry() {
    int tid = blockIdx.x * blockDim.x + threadIdx.x;  // 8192 lanes
    int b = tid >> 11;
    int dn = tid & 2047;
    float h = 0.f;
    #pragma unroll 4
    for (int c = 0; c < NCH; c++) {
        int idx = (b*NCH + c)*2048 + dn;
        g_hin[idx] = h;
        h = g_P[idx]*h + g_F[idx];
    }
}

// ---------------- K5: scan phase 3 — recompute with carry, emit gated y ----------------
__global__ void __launch_bounds__(512) k_scan3(const float* __restrict__ Alog,
                                               const float* __restrict__ Dsk) {
    int tid = threadIdx.x;
    int d = tid >> 2, ng = tid & 3;
    int b = blockIdx.x / NCH, c = blockIdx.x % NCH;
    const float* al = Alog + d*DS + ng*4;
    float A0 = -__expf(al[0]), A1 = -__expf(al[1]);
    float A2 = -__expf(al[2]), A3 = -__expf(al[3]);
    float Dd = Dsk[d];
    int base = b*LSEQ + c*TC;
    int o = ((b*NCH + c)*DI + d)*DS + ng*4;
    float4 h4 = *(const float4*)(g_hin + o);
    float h0 = h4.x, h1 = h4.y, h2 = h4.z, h3 = h4.w;
    float de = g_delta[base*DI + d];
    float uu = g_u[base*DI + d];
    float zz = g_xz[base*(2*DI) + DI + d];
    float4 Bv = *(const float4*)(g_Bm + base*DS + ng*4);
    float4 Cv = *(const float4*)(g_Cm + base*DS + ng*4);
    #pragma unroll 2
    for (int i = 0; i < TC; i++) {
        float de_c = de, uu_c = uu, zz_c = zz;
        float4 B_c = Bv, C_c = Cv;
        int ln = base + ((i + 1 < TC) ? (i + 1) : i);
        de = g_delta[ln*DI + d];
        uu = g_u[ln*DI + d];
        zz = g_xz[ln*(2*DI) + DI + d];
        Bv = *(const float4*)(g_Bm + ln*DS + ng*4);
        Cv = *(const float4*)(g_Cm + ln*DS + ng*4);
        float du = de_c * uu_c;
        h0 = __expf(de_c*A0)*h0 + du*B_c.x;
        h1 = __expf(de_c*A1)*h1 + du*B_c.y;
        h2 = __expf(de_c*A2)*h2 + du*B_c.z;
        h3 = __expf(de_c*A3)*h3 + du*B_c.w;
        float yp = h0*C_c.x + h1*C_c.y + h2*C_c.z + h3*C_c.w;
        yp += __shfl_down_sync(0xffffffffu, yp, 2, 4);
        yp += __shfl_down_sync(0xffffffffu, yp, 1, 4);
        if (ng == 0) {
            g_y[(base + i)*DI + d] = (yp + uu_c*Dd) * silu_f(zz_c);
        }
    }
}

// ---------------- K6: h += y @ out_proj_w.T ----------------
__global__ void __launch_bounds__(256) k_outproj(const float* __restrict__ W) {
    __shared__ float swT[DI*65];   // transposed + padded
    __shared__ float sy[4*DI];
    int tid = threadIdx.x;
    for (int i = tid; i < DM*DI; i += 256) {
        int m = i / DI, dd = i % DI;
        swT[dd*65 + m] = W[i];
    }
    __syncthreads();
    int tok0 = blockIdx.x * 32;
    int t4 = tid >> 6, m = tid & 63;
    for (int g = 0; g < 8; g++) {
        __syncthreads();
        for (int i = tid; i < 4*DI; i += 256) sy[i] = g_y[(tok0 + g*4)*DI + i];
        __syncthreads();
        float acc = 0.f;
        #pragma unroll 4
        for (int dd = 0; dd < DI; dd++) acc += sy[t4*DI + dd] * swT[dd*65 + m];
        int tok = tok0 + g*4 + t4;
        g_h[tok*DM + m] += acc;
    }
}

// ---------------- K7: mean pool over L + classifier ----------------
__global__ void __launch_bounds__(256) k_head(const float* __restrict__ wc,
                                              const float* __restrict__ bc,
                                              float* __restrict__ out) {
    __shared__ float red[256];
    __shared__ float pooled[DM];
    int b = blockIdx.x;
    int tid = threadIdx.x;
    int m = tid & 63, part = tid >> 6;
    float acc = 0.f;
    for (int l = part; l < LSEQ; l += 4) acc += g_h[(b*LSEQ + l)*DM + m];
    red[tid] = acc;
    __syncthreads();
    if (part == 0)
        pooled[m] = (red[m] + red[m+64] + red[m+128] + red[m+192]) * (1.f / LSEQ);
    __syncthreads();
    if (tid < NOUT) {
        float s = bc[tid];
        #pragma unroll
        for (int k = 0; k < DM; k++) s += pooled[k] * wc[tid*DM + k];
        out[b*NOUT + tid] = s;
    }
}

// ---------------- launcher ----------------
extern "C" void kernel_launch(void* const* d_in, const int* in_sizes, int n_in,
                              void* d_out, int out_size) {
    const float* x    = (const float*)d_in[0];
    const float* w_in = (const float*)d_in[1];
    const float* b_in = (const float*)d_in[2];
    const float* ipw  = (const float*)d_in[3];
    const float* cw   = (const float*)d_in[4];
    const float* cb   = (const float*)d_in[5];
    const float* xpw  = (const float*)d_in[6];
    const float* dpw  = (const float*)d_in[7];
    const float* dpb  = (const float*)d_in[8];
    const float* Alog = (const float*)d_in[9];
    const float* Dsk  = (const float*)d_in[10];
    const float* opw  = (const float*)d_in[11];
    const float* wc   = (const float*)d_in[12];
    const float* bc   = (const float*)d_in[13];
    float* out = (float*)d_out;

    k_linear_in<<<NTOK/64, 256>>>(x, w_in, b_in);
    for (int i = 0; i < 2; i++) {
        k_in_proj<<<NTOK/32, 256>>>(ipw + i*2*DI*DM);
        k_pre<<<NTOK/32, 256>>>(cw + i*DI*NCONV, cb + i*DI,
                                xpw + i*NDBL*DI, dpw + i*DI*DTR, dpb + i*DI);
        k_scan1<<<BZ*NCH, 512>>>(Alog + i*DI*DS);
        k_carry<<<16, 512>>>();
        k_scan3<<<BZ*NCH, 512>>>(Alog + i*DI*DS, Dsk + i*DI);
        k_outproj<<<NTOK/32, 256>>>(opw + i*DM*DI);
    }
    k_head<<<BZ, 256>>>(wc, bc, out);
}